// round 4
// baseline (speedup 1.0000x reference)
#include <cuda_runtime.h>
#include <cuda_bf16.h>

// RoIPooling: crop_and_resize bilinear, POOL 7x7.
// feature_map: [B=8, H=64, W=64, C=256] fp32
// roi_bboxes:  [B=8, N=1000, 4] fp32 (y1,x1,y2,x2) normalized
// out:         [B, N, 7, 7, C] fp32
//
// R4: one warp per (box, py, channel-half), px processed in PAIRS.
// Each iteration front-batches 8 independent LDG.128 (two px * 4 corners)
// so the active-issue phase per memory wait doubles vs R3 — covering L2
// latency (~250cyc) even at reduced occupancy. 112000 warps.

namespace {

constexpr int Hc = 64;
constexpr int Wc = 64;
constexpr int Cc = 256;          // channels
constexpr int CQ = Cc / 4;       // 64 float4 per pixel
constexpr int PH = 7;
constexpr int PW = 7;
constexpr int Bc = 8;
constexpr int Nc = 1000;
constexpr int NUM_WARPS = Bc * Nc * PH * 2;     // 112000 (2 channel-halves)
constexpr int WARPS_PER_BLOCK = 8;
constexpr int THREADS = WARPS_PER_BLOCK * 32;

// bilinear combine of one float4 corner set
__device__ __forceinline__ float4 lerp2d(const float4 a, const float4 b,
                                         const float4 c, const float4 d,
                                         const float wx, const float wy)
{
    float4 r;
    float top, bot;
    top = a.x + (b.x - a.x) * wx;  bot = c.x + (d.x - c.x) * wx;
    r.x = top + (bot - top) * wy;
    top = a.y + (b.y - a.y) * wx;  bot = c.y + (d.y - c.y) * wx;
    r.y = top + (bot - top) * wy;
    top = a.z + (b.z - a.z) * wx;  bot = c.z + (d.z - c.z) * wx;
    r.z = top + (bot - top) * wy;
    top = a.w + (b.w - a.w) * wx;  bot = c.w + (d.w - c.w) * wx;
    r.w = top + (bot - top) * wy;
    return r;
}

__global__ __launch_bounds__(THREADS) void roi_pool_kernel(
    const float* __restrict__ fm,
    const float* __restrict__ boxes,
    float* __restrict__ out)
{
    const int gwarp = (blockIdx.x * WARPS_PER_BLOCK) + (threadIdx.x >> 5);
    const int lane = threadIdx.x & 31;

    // gwarp = (box * PH + py) * 2 + half
    const int half = gwarp & 1;
    const int row  = gwarp >> 1;       // box * PH + py
    const int py   = row % PH;
    const int box  = row / PH;         // 0 .. B*N-1 (batch-major, matches output)
    const int b    = box / Nc;

    // Box coords (16B aligned)
    const float4 bc = __ldg(reinterpret_cast<const float4*>(boxes) + box);
    const float by1 = bc.x, bx1 = bc.y, by2 = bc.z, bx2 = bc.w;

    const float hm1 = (float)(Hc - 1);
    const float wm1 = (float)(Wc - 1);

    // ---- y math: once per warp (matches reference op order) ----
    const float y = by1 * hm1 + (float)py * ((by2 - by1) * hm1 / (float)(PH - 1));
    const float y0f = floorf(y);
    const float wy  = y - y0f;
    int y0 = (int)y0f;  y0 = min(max(y0, 0), Hc - 1);
    const int y1i = min(y0 + 1, Hc - 1);
    const bool valid_y = (y >= 0.0f) & (y <= hm1);

    // quad index within the pixel handled by this lane
    const int q = half * 32 + lane;

    // 32-bit float4 offsets (fm = 8.4M float4, out = 100.4M float4, both < 2^31)
    const float4* fm4 = reinterpret_cast<const float4*>(fm);
    const int bbase   = b * (Hc * Wc * CQ);
    const int rowT    = bbase + y0  * (Wc * CQ) + q;   // top row, this lane's quad
    const int rowB    = bbase + y1i * (Wc * CQ) + q;   // bottom row

    // ---- x constants: once per warp ----
    const float xbase = bx1 * wm1;
    const float dx    = (bx2 - bx1) * wm1 / (float)(PW - 1);

    unsigned int oofs = (unsigned int)row * (PW * CQ) + q;
    float4* o4 = reinterpret_cast<float4*>(out);

    // helper lambda-free per-px x computation
    #define XMATH(PX, X0Q, X1Q, WX, VALID)                         \
        {                                                           \
            const float xv  = xbase + (float)(PX) * dx;             \
            const float xf  = floorf(xv);                           \
            (WX) = xv - xf;                                         \
            int xi = (int)xf;  xi = min(max(xi, 0), Wc - 1);        \
            (X0Q) = xi * CQ;                                        \
            (X1Q) = min(xi + 1, Wc - 1) * CQ;                       \
            (VALID) = valid_y & (xv >= 0.0f) & (xv <= wm1);         \
        }

    #pragma unroll 1
    for (int px = 0; px < PW - 1; px += 2) {
        int   x0qA, x1qA, x0qB, x1qB;
        float wxA, wxB;
        bool  vA, vB;
        XMATH(px,     x0qA, x1qA, wxA, vA);
        XMATH(px + 1, x0qB, x1qB, wxB, vB);

        // Front-batch all 8 independent loads (MLP = 8)
        const float4 aA = __ldg(fm4 + rowT + x0qA);
        const float4 bA = __ldg(fm4 + rowT + x1qA);
        const float4 cA = __ldg(fm4 + rowB + x0qA);
        const float4 dA = __ldg(fm4 + rowB + x1qA);
        const float4 aB = __ldg(fm4 + rowT + x0qB);
        const float4 bB = __ldg(fm4 + rowT + x1qB);
        const float4 cB = __ldg(fm4 + rowB + x0qB);
        const float4 dB = __ldg(fm4 + rowB + x1qB);

        float4 rA = lerp2d(aA, bA, cA, dA, wxA, wy);
        float4 rB = lerp2d(aB, bB, cB, dB, wxB, wy);
        if (!vA) { rA.x = rA.y = rA.z = rA.w = 0.f; }
        if (!vB) { rB.x = rB.y = rB.z = rB.w = 0.f; }

        // Streaming stores: keep the 401MB output stream from evicting the
        // 33.5MB feature map out of L2 (gathers depend on L2 hits).
        __stcs(o4 + oofs, rA);
        __stcs(o4 + oofs + CQ, rB);
        oofs += 2 * CQ;
    }

    // tail px = 6
    {
        int   x0q, x1q;
        float wx;
        bool  v;
        XMATH(PW - 1, x0q, x1q, wx, v);

        const float4 a = __ldg(fm4 + rowT + x0q);
        const float4 bq= __ldg(fm4 + rowT + x1q);
        const float4 c = __ldg(fm4 + rowB + x0q);
        const float4 d = __ldg(fm4 + rowB + x1q);

        float4 r = lerp2d(a, bq, c, d, wx, wy);
        if (!v) { r.x = r.y = r.z = r.w = 0.f; }
        __stcs(o4 + oofs, r);
    }
    #undef XMATH
}

} // namespace

extern "C" void kernel_launch(void* const* d_in, const int* in_sizes, int n_in,
                              void* d_out, int out_size) {
    const float* fm    = (const float*)d_in[0];
    const float* boxes = (const float*)d_in[1];
    float* out         = (float*)d_out;

    const int blocks = NUM_WARPS / WARPS_PER_BLOCK;  // 14000, exact
    roi_pool_kernel<<<blocks, THREADS>>>(fm, boxes, out);
}

// round 5
// speedup vs baseline: 1.5802x; 1.5802x over previous
#include <cuda_runtime.h>
#include <cuda_bf16.h>

// RoIPooling: crop_and_resize bilinear, POOL 7x7.
// feature_map: [B=8, H=64, W=64, C=256] fp32
// roi_bboxes:  [B=8, N=1000, 4] fp32 (y1,x1,y2,x2) normalized
// out:         [B, N, 7, 7, C] fp32
//
// R5: R3 skeleton (one warp per (box,py,channel-half), 4-load batch, 32 regs,
// 8 CTAs/SM) + lane-parallel x-precompute: lane i computes px=i's
// {x0q|x1q, wx, mask} once; loop body broadcasts via 3 SHFLs instead of
// ~10 ALU ops per iteration. Validity applied as exact *1.0/0.0 multiply.

namespace {

constexpr int Hc = 64;
constexpr int Wc = 64;
constexpr int Cc = 256;          // channels
constexpr int CQ = Cc / 4;       // 64 float4 per pixel
constexpr int PH = 7;
constexpr int PW = 7;
constexpr int Bc = 8;
constexpr int Nc = 1000;
constexpr int NUM_WARPS = Bc * Nc * PH * 2;     // 112000 (2 channel-halves)
constexpr int WARPS_PER_BLOCK = 8;
constexpr int THREADS = WARPS_PER_BLOCK * 32;

__global__ __launch_bounds__(THREADS, 8) void roi_pool_kernel(
    const float* __restrict__ fm,
    const float* __restrict__ boxes,
    float* __restrict__ out)
{
    const int gwarp = (blockIdx.x * WARPS_PER_BLOCK) + (threadIdx.x >> 5);
    const int lane = threadIdx.x & 31;

    // gwarp = (box * PH + py) * 2 + half   (grid is exact: no bounds guard)
    const int half = gwarp & 1;
    const int row  = gwarp >> 1;       // box * PH + py
    const int py   = row % PH;
    const int box  = row / PH;         // 0 .. B*N-1 (batch-major, matches output)
    const int b    = box / Nc;

    // Box coords (16B aligned)
    const float4 bc = __ldg(reinterpret_cast<const float4*>(boxes) + box);
    const float by1 = bc.x, bx1 = bc.y, by2 = bc.z, bx2 = bc.w;

    const float hm1 = (float)(Hc - 1);
    const float wm1 = (float)(Wc - 1);

    // ---- y math: once per warp (matches reference op order) ----
    const float y = by1 * hm1 + (float)py * ((by2 - by1) * hm1 / (float)(PH - 1));
    const float y0f = floorf(y);
    const float wy  = y - y0f;
    int y0 = (int)y0f;  y0 = min(max(y0, 0), Hc - 1);
    const int y1i = min(y0 + 1, Hc - 1);
    const bool valid_y = (y >= 0.0f) & (y <= hm1);

    // quad index within the pixel handled by this lane
    const int q = half * 32 + lane;

    // 32-bit float4 offsets (fm = 8.4M float4, out = 100.4M float4, both < 2^31)
    const float4* fm4 = reinterpret_cast<const float4*>(fm);
    const int bbase   = b * (Hc * Wc * CQ);
    const int rowT    = bbase + y0  * (Wc * CQ) + q;   // top row, this lane's quad
    const int rowB    = bbase + y1i * (Wc * CQ) + q;   // bottom row

    // ---- x math: lane-parallel precompute. Lane i handles px = i (0..6 used;
    // lanes 7..31 compute harmless garbage that is never read). ----
    const float xbase = bx1 * wm1;
    const float dx    = (bx2 - bx1) * wm1 / (float)(PW - 1);

    const float xv  = xbase + (float)lane * dx;     // same op order as reference
    const float xf  = floorf(xv);
    const float wx_l = xv - xf;
    int xi = (int)xf;  xi = min(max(xi, 0), Wc - 1);
    const int x0q_l = xi * CQ;                       // <= 4032, fits 16 bits
    const int x1q_l = min(xi + 1, Wc - 1) * CQ;
    const int packed_l = x0q_l | (x1q_l << 16);
    const float mask_l = (valid_y & (xv >= 0.0f) & (xv <= wm1)) ? 1.0f : 0.0f;

    unsigned int oofs = (unsigned int)row * (PW * CQ) + q;
    float4* o4 = reinterpret_cast<float4*>(out);

    #pragma unroll 1
    for (int px = 0; px < PW; ++px) {
        const int   pk = __shfl_sync(0xffffffffu, packed_l, px);
        const float wx = __shfl_sync(0xffffffffu, wx_l, px);
        const float m  = __shfl_sync(0xffffffffu, mask_l, px);
        const int x0q = pk & 0xFFFF;
        const int x1q = pk >> 16;

        // Front-batch the 4 corner loads (MLP = 4 per warp, ~14 warps/SMSP)
        const float4 a = __ldg(fm4 + rowT + x0q);
        const float4 bq= __ldg(fm4 + rowT + x1q);
        const float4 c = __ldg(fm4 + rowB + x0q);
        const float4 d = __ldg(fm4 + rowB + x1q);

        float4 r;
        {
            float top, bot;
            top = a.x + (bq.x - a.x) * wx;  bot = c.x + (d.x - c.x) * wx;
            r.x = (top + (bot - top) * wy) * m;
            top = a.y + (bq.y - a.y) * wx;  bot = c.y + (d.y - c.y) * wx;
            r.y = (top + (bot - top) * wy) * m;
            top = a.z + (bq.z - a.z) * wx;  bot = c.z + (d.z - c.z) * wx;
            r.z = (top + (bot - top) * wy) * m;
            top = a.w + (bq.w - a.w) * wx;  bot = c.w + (d.w - c.w) * wx;
            r.w = (top + (bot - top) * wy) * m;
        }

        // Streaming store: keep the 401MB output stream from evicting the
        // 33.5MB feature map out of L2 (gathers depend on L2 hits).
        __stcs(o4 + oofs, r);
        oofs += CQ;
    }
}

} // namespace

extern "C" void kernel_launch(void* const* d_in, const int* in_sizes, int n_in,
                              void* d_out, int out_size) {
    const float* fm    = (const float*)d_in[0];
    const float* boxes = (const float*)d_in[1];
    float* out         = (float*)d_out;

    const int blocks = NUM_WARPS / WARPS_PER_BLOCK;  // 14000, exact
    roi_pool_kernel<<<blocks, THREADS>>>(fm, boxes, out);
}